// round 6
// baseline (speedup 1.0000x reference)
#include <cuda_runtime.h>
#include <math.h>

#define SIMS 2048
#define NB   256
#define MID  512
#define G    64      // persistent CTAs
#define TPB  512
#define TPC  4       // tasks per CTA per step (4*64 = 256 winner slots)
#define ORPC 32      // output rows per CTA = SIMS/G
#define GB   256     // k_base grid
#define RPCB 8
#define CSTR 32      // floats between common groups (128B line stride)
#define NGRP 128     // 128 float4-groups = 512 floats

// ---------------- device scratch ----------------
__device__ __align__(16) float g_y [SIMS * MID];       // base = xs@w1+b1
__device__ __align__(16) float g_y2[SIMS * MID];       // base minus fw==0 cols
__device__ __align__(16) float g_w2g[NB * MID];        // gamma[j]*w2[j][c], c-major
__device__ __align__(16) float g_u[NB];
__device__ __align__(16) float g_commonX[2 * NGRP * CSTR]; // strided dbl-buffer
__device__ float g_Ac[NB];
__device__ float g_bc[NB];
__device__ int   g_winner[NB * NB];                    // [t][c] = max s, else -1
__device__ int   g_fw[NB];
__device__ int   g_tasks[NB * NB];                     // [t][i] = (s<<8)|c, -1 pad
__device__ int   g_newlist[NB];
__device__ int   g_newstart[NB + 1];
__device__ unsigned g_cnt;

// ---------------- grid barrier (monotonic counter) ----------------
__device__ __forceinline__ void gbar(unsigned &tgt) {
    __syncthreads();
    if (threadIdx.x == 0) {
        __threadfence();
        atomicAdd(&g_cnt, 1u);
        while (*(volatile unsigned*)&g_cnt < tgt) { }
        __threadfence();
    }
    __syncthreads();
    tgt += G;
}

// ---------------- fast erf-GELU (A&S 7.1.26, |err|<=1.5e-7) ----------------
__device__ __forceinline__ float gelu_f(float x) {
    float z  = 0.70710678118654752f * x;
    float az = fabsf(z);
    float t  = __fdividef(1.0f, fmaf(0.3275911f, az, 1.0f));
    float p  = t * fmaf(t, fmaf(t, fmaf(t, fmaf(t, 1.061405429f, -1.453152027f),
                                        1.421413741f), -0.284496736f), 0.254829592f);
    float ex = __expf(-z * z);
    float E  = fmaf(-p, ex, 1.0f);
    float e  = copysignf(E, x);
    float hx = 0.5f * x;
    return fmaf(hx, e, hx);
}

// ---------------- init kernels ----------------
__global__ void k_init1(const float* __restrict__ w2,
                        const float* __restrict__ gamma) {
    int idx = blockIdx.x * blockDim.x + threadIdx.x;   // 131072 threads
    if (idx < NB * NB) g_winner[idx] = -1;
    {   // w2g[c*MID + j] = gamma[j] * w2[j*NB + c]
        int c = idx >> 9, j = idx & (MID - 1);
        g_w2g[idx] = gamma[j] * w2[j * NB + c];
    }
    if (idx < 2 * NGRP * CSTR) g_commonX[idx] = 0.f;
    if (idx < NB)  g_u[idx] = 0.f;
    if (idx == 0)  g_cnt = 0u;
}

__global__ void k_init2(const int* __restrict__ ids) {
    int idx = blockIdx.x * blockDim.x + threadIdx.x;   // idx = s*256 + t
    int s = idx >> 8;
    int t = idx & (NB - 1);
    int c = ids[idx];
    atomicMax(&g_winner[t * NB + c], s);
}

__global__ void k_init3() {
    __shared__ int fw[NB];
    __shared__ int cnt[NB];
    __shared__ int start[NB + 1];
    __shared__ int offs[NB];
    int c = threadIdx.x;                 // 256 threads
    cnt[c] = 0;
    int f = 1 << 30;
    for (int t = 0; t < NB; t++)
        if (g_winner[t * NB + c] >= 0) { f = t; break; }
    g_fw[c] = f;
    fw[c] = f;
    __syncthreads();
    if (f < NB) atomicAdd(&cnt[f], 1);
    __syncthreads();
    if (c == 0) {
        int pos = 0;
        for (int t = 0; t < NB; t++) { start[t] = pos; pos += cnt[t]; }
        start[NB] = pos;
    }
    __syncthreads();
    g_newstart[c] = start[c];
    if (c == 0) g_newstart[NB] = start[NB];
    offs[c] = start[c];
    __syncthreads();
    if (f < NB) {
        int p = atomicAdd(&offs[f], 1);
        g_newlist[p] = c;
    }
}

// deterministic compacted task list per step
__global__ void k_task() {
    __shared__ int wcnt[8];
    int t = blockIdx.x, c = threadIdx.x;   // 256 threads
    int s = g_winner[t * NB + c];
    int valid = (s >= 0);
    unsigned mask = __ballot_sync(0xffffffffu, valid);
    int w = c >> 5, lane = c & 31;
    if (lane == 0) wcnt[w] = __popc(mask);
    g_tasks[t * NB + c] = -1;
    __syncthreads();
    int base = 0;
    for (int k = 0; k < w; k++) base += wcnt[k];
    if (valid) {
        int pos = base + __popc(mask & ((1u << lane) - 1u));
        g_tasks[t * NB + pos] = (s << 8) | c;
    }
}

__global__ void k_init5(const float* __restrict__ w2,
                        const float* __restrict__ gamma,
                        const float* __restrict__ beta,
                        const float* __restrict__ b2) {
    __shared__ float sa[4], sb[4];
    int c = blockIdx.x;
    int tid = threadIdx.x;               // 128 threads
    float a = 0.f, bs = 0.f;
    for (int j = tid; j < MID; j += 128) {
        float w = w2[j * NB + c];
        a  = fmaf(gamma[j], w, a);
        bs = fmaf(beta[j],  w, bs);
    }
#pragma unroll
    for (int off = 16; off; off >>= 1) {
        a  += __shfl_xor_sync(0xffffffffu, a,  off);
        bs += __shfl_xor_sync(0xffffffffu, bs, off);
    }
    if ((tid & 31) == 0) { sa[tid >> 5] = a; sb[tid >> 5] = bs; }
    __syncthreads();
    if (tid == 0) {
        g_Ac[c] = sa[0] + sa[1] + sa[2] + sa[3];
        g_bc[c] = sb[0] + sb[1] + sb[2] + sb[3] + b2[c];
    }
}

// base = xs@w1 + b1 ; y2 = b1 + columns with fw>=1
__global__ void __launch_bounds__(TPB) k_base(const float* __restrict__ xs,
                                              const float* __restrict__ w1,
                                              const float* __restrict__ b1) {
    __shared__ float xsS[RPCB * NB];
    int tid = threadIdx.x;
    int row0 = blockIdx.x * RPCB;
    for (int i = tid; i < RPCB * NB; i += TPB) xsS[i] = xs[row0 * NB + i];
    __syncthreads();

    float acc[RPCB];
#pragma unroll
    for (int r = 0; r < RPCB; r++) acc[r] = 0.f;
#pragma unroll 8
    for (int c = 0; c < NB; c++) {
        float w = w1[c * MID + tid];
#pragma unroll
        for (int r = 0; r < RPCB; r++)
            acc[r] = fmaf(xsS[r * NB + c], w, acc[r]);
    }
    float bb = b1[tid];
#pragma unroll
    for (int r = 0; r < RPCB; r++)
        g_y[(row0 + r) * MID + tid] = acc[r] + bb;

    float y2a[RPCB];
#pragma unroll
    for (int r = 0; r < RPCB; r++) y2a[r] = bb;
    int st = g_newstart[1], en = g_newstart[NB];
    for (int i = st; i < en; i++) {
        int c = g_newlist[i];
        float w = w1[c * MID + tid];
#pragma unroll
        for (int r = 0; r < RPCB; r++)
            y2a[r] = fmaf(xsS[r * NB + c], w, y2a[r]);
    }
#pragma unroll
    for (int r = 0; r < RPCB; r++)
        g_y2[(row0 + r) * MID + tid] = y2a[r];
}

// ---------------- main persistent kernel ----------------
__global__ void __launch_bounds__(TPB) k_main(const float* __restrict__ xs,
                                              const float* __restrict__ w1,
                                              float* __restrict__ out) {
    __shared__ __align__(16) float cS[MID];
    __shared__ __align__(16) float4 rS4[NGRP];
    __shared__ float sred[TPC * 4 * 3];
    __shared__ float pS[TPC];
    __shared__ float uoldS[TPC];
    __shared__ int   taskS[TPC * NB];
    __shared__ int   nsS[NB + 1];
    __shared__ float uS[NB];
    __shared__ int   fwS[NB];

    const int tid  = threadIdx.x;
    const int b    = blockIdx.x;
    const int row0 = b * ORPC;
    const int lane = tid & 31;
    const int grp  = tid >> 7;                // task slot 0..3
    const int gtid = tid & 127;               // thread within task
    const int gw   = (tid >> 5) & 3;          // warp within task

    // preload this CTA's TPC tasks for every step
    for (int i = tid; i < TPC * NB; i += TPB) {
        int t = i >> 2, k = i & 3;
        taskS[i] = g_tasks[t * NB + TPC * b + k];
    }
    if (tid <= NB) nsS[tid] = g_newstart[tid];
    if (tid < NB)  fwS[tid] = g_fw[tid];
    __syncthreads();

    unsigned tgt = G;
    float4 rprev = make_float4(0.f, 0.f, 0.f, 0.f);

    for (int t = 0; t < NB; t++) {
        // ---- step setup: load common, prefetch w1 cols + uold ----
        if (tid < NGRP) {
            float4 cv = *(const float4*)&g_commonX[(t & 1) * (NGRP * CSTR) + tid * CSTR];
            ((float4*)cS)[tid] = cv;
        }
        int tcol[TPC];
        float w1p[TPC];
#pragma unroll
        for (int k = 0; k < TPC; k++) {
            int task = taskS[t * TPC + k];
            tcol[k] = (task >= 0) ? (task & 255) : -1;
            w1p[k]  = (task >= 0) ? w1[(size_t)tcol[k] * MID + tid] : 0.f;
        }
        if (tid < TPC) {
            int task = taskS[t * TPC + tid];
            float uo = (task >= 0) ? g_u[task & 255] : 0.f;
            uoldS[tid] = uo;
            pS[tid]    = uo;          // default: delta = 0 for empty slots
        }
        int mytask = taskS[t * TPC + grp];
        const float* yb = (t == 0) ? g_y : g_y2;
        __syncthreads();

        // ---- phase A: 4 winner rows, 128 threads each ----
        if (mytask >= 0) {
            int c    = mytask & 255;
            int srow = mytask >> 8;
            float4 yv = ((const float4*)(yb + (size_t)srow * MID))[gtid];
            float4 cv = ((const float4*)cS)[gtid];
            float4 wv = ((const float4*)(g_w2g + (size_t)c * MID))[gtid];
            float g0 = gelu_f(yv.x + cv.x);
            float g1 = gelu_f(yv.y + cv.y);
            float g2 = gelu_f(yv.z + cv.z);
            float g3 = gelu_f(yv.w + cv.w);
            float s = (g0 + g1) + (g2 + g3);
            float q = fmaf(g0, g0, g1 * g1) + fmaf(g2, g2, g3 * g3);
            float d = fmaf(g0, wv.x, g1 * wv.y) + fmaf(g2, wv.z, g3 * wv.w);
#pragma unroll
            for (int off = 16; off; off >>= 1) {
                s += __shfl_xor_sync(0xffffffffu, s, off);
                q += __shfl_xor_sync(0xffffffffu, q, off);
                d += __shfl_xor_sync(0xffffffffu, d, off);
            }
            if (lane == 0) {
                sred[(grp * 4 + gw) * 3 + 0] = s;
                sred[(grp * 4 + gw) * 3 + 1] = q;
                sred[(grp * 4 + gw) * 3 + 2] = d;
            }
        }
        __syncthreads();

        if (gtid == 0 && mytask >= 0) {
            int c = mytask & 255;
            float S = 0.f, Q = 0.f, D = 0.f;
#pragma unroll
            for (int k = 0; k < 4; k++) {
                S += sred[(grp * 4 + k) * 3 + 0];
                Q += sred[(grp * 4 + k) * 3 + 1];
                D += sred[(grp * 4 + k) * 3 + 2];
            }
            float mu  = S * (1.f / 512.f);
            float var = fmaf(-mu, mu, Q * (1.f / 512.f));
            float inv = rsqrtf(var + 1e-5f);
            float logit = fmaf(inv, fmaf(-mu, g_Ac[c], D), g_bc[c]);
            float p = __fdividef(1.f, 1.f + __expf(-logit));
            g_u[c] = p;
            pS[grp] = p;
        }
        __syncthreads();

        // ---- delta of common: per-thread FMA with prefetched w1 ----
        {
            float r = 0.f;
#pragma unroll
            for (int k = 0; k < TPC; k++)
                r = fmaf(pS[k] - uoldS[k], w1p[k], r);
            ((float*)rS4)[tid] = r;
        }
        __syncthreads();
        if (tid < NGRP) {
            float4 r4 = rS4[tid];
            float4 add = make_float4(r4.x + rprev.x, r4.y + rprev.y,
                                     r4.z + rprev.z, r4.w + rprev.w);
            rprev = r4;
            atomicAdd((float4*)&g_commonX[((t + 1) & 1) * (NGRP * CSTR) + tid * CSTR], add);
        }

        // ---- rare first-write corrections for t>=1 ----
        if (t > 0) {
            int st = nsS[t], en = nsS[t + 1];
            for (int i = st; i < en; i++) {
                int cc = g_newlist[i];
                float w = w1[cc * MID + tid];
                for (int rl = 0; rl < ORPC; rl++) {
                    float xv = xs[(row0 + rl) * NB + cc];
                    g_y2[(size_t)(row0 + rl) * MID + tid] -= xv * w;
                }
            }
        }

        gbar(tgt);   // one barrier: g_u, RED-adds, y2 corrections all visible
    }

    // ---- output ----
    if (tid < NB) uS[tid] = g_u[tid];
    __syncthreads();
    for (int i = tid; i < ORPC * NB; i += TPB) {
        int c2 = i & (NB - 1);
        int rl = i >> 8;
        float v = (fwS[c2] < NB) ? uS[c2] : xs[(row0 + rl) * NB + c2];
        out[(row0 + rl) * NB + c2] = v;
    }
}

// ---------------- launch ----------------
extern "C" void kernel_launch(void* const* d_in, const int* in_sizes, int n_in,
                              void* d_out, int out_size) {
    const float* xs    = (const float*)d_in[0];
    const int*   ids   = (const int*)d_in[1];
    const float* w1    = (const float*)d_in[2];
    const float* b1    = (const float*)d_in[3];
    const float* gamma = (const float*)d_in[4];
    const float* beta  = (const float*)d_in[5];
    const float* w2    = (const float*)d_in[6];
    const float* b2    = (const float*)d_in[7];
    float* out = (float*)d_out;

    k_init1<<<512, 256>>>(w2, gamma);
    k_init2<<<SIMS * NB / 256, 256>>>(ids);
    k_init3<<<1, 256>>>();
    k_task<<<NB, 256>>>();
    k_init5<<<NB, 128>>>(w2, gamma, beta, b2);
    k_base<<<GB, TPB>>>(xs, w1, b1);
    k_main<<<G, TPB>>>(xs, w1, out);
}